// round 1
// baseline (speedup 1.0000x reference)
#include <cuda_runtime.h>
#include <math.h>

#define MAX_N   131072
#define NGRAPH  256
#define MAXSEG  2048

// Scratch (static __device__ arrays — no allocation allowed)
__device__ float d_p[MAX_N];        // x[i] . w_rel
__device__ float d_r[MAX_N];        // x[i] . w_root
__device__ float d_s[MAX_N];        // segment-summed p over edges (also reused as w scratch for huge segments)
__device__ float d_score[MAX_N];    // tanh score
__device__ int   d_starts[NGRAPH + 1];

// ---------------------------------------------------------------------------
// K0: per-node dot products p = x.w_rel, r = x.w_root ; zero s.
// One warp per node, float2 vectorized (64 floats = 32 lanes x float2).
// ---------------------------------------------------------------------------
__global__ void k_node_dots(const float* __restrict__ x,
                            const float* __restrict__ w_rel,
                            const float* __restrict__ w_root,
                            int N) {
    int warp = (int)((blockIdx.x * (unsigned)blockDim.x + threadIdx.x) >> 5);
    int lane = threadIdx.x & 31;
    if (warp >= N) return;
    const float2* xv = (const float2*)(x + (size_t)warp * 64);
    float2 v  = xv[lane];
    float2 wr = ((const float2*)w_rel)[lane];
    float2 wt = ((const float2*)w_root)[lane];
    float a = v.x * wr.x + v.y * wr.y;
    float b = v.x * wt.x + v.y * wt.y;
#pragma unroll
    for (int o = 16; o; o >>= 1) {
        a += __shfl_xor_sync(0xffffffffu, a, o);
        b += __shfl_xor_sync(0xffffffffu, b, o);
    }
    if (lane == 0) {
        d_p[warp] = a;
        d_r[warp] = b;
        d_s[warp] = 0.0f;
    }
}

// ---------------------------------------------------------------------------
// K1: edge scatter  s[dst] += p[src]  (scalar per edge -- the big win vs
// materializing agg[N,64]). Vectorized int4 loads of src/dst.
// ---------------------------------------------------------------------------
__global__ void k_edge_scatter4(const int* __restrict__ ei, int E) {
    int t = blockIdx.x * blockDim.x + threadIdx.x;
    int E4 = E >> 2;
    if (t < E4) {
        int4 s4 = ((const int4*)ei)[t];
        int4 d4 = ((const int4*)(ei + E))[t];
        atomicAdd(&d_s[d4.x], d_p[s4.x]);
        atomicAdd(&d_s[d4.y], d_p[s4.y]);
        atomicAdd(&d_s[d4.z], d_p[s4.z]);
        atomicAdd(&d_s[d4.w], d_p[s4.w]);
    }
}

__global__ void k_edge_scatter1(const int* __restrict__ ei, int E) {
    int t = blockIdx.x * blockDim.x + threadIdx.x;
    if (t < E) {
        atomicAdd(&d_s[ei[E + t]], d_p[ei[t]]);
    }
}

// ---------------------------------------------------------------------------
// K2: score = tanh(s + b_rel + r); detect segment starts of the sorted batch.
// ---------------------------------------------------------------------------
__global__ void k_score_starts(const int* __restrict__ batch,
                               const float* __restrict__ b_rel,
                               int N) {
    int i = blockIdx.x * blockDim.x + threadIdx.x;
    if (i >= N) return;
    d_score[i] = tanhf(d_s[i] + b_rel[0] + d_r[i]);
    int bi = batch[i];
    if (i == 0) {
        for (int g = 0; g <= bi; ++g) d_starts[g] = 0;
    } else {
        int bp = batch[i - 1];
        for (int g = bp + 1; g <= bi; ++g) d_starts[g] = i;
    }
    if (i == N - 1) {
        for (int g = bi + 1; g <= NGRAPH; ++g) d_starts[g] = N;
    }
}

// ---------------------------------------------------------------------------
// K3: per-graph block: exact top-k selection (rank with the reference's
// lexsort tie-break: score desc, index asc) + fused weighted mean pooling.
// Exactly k nodes are kept (ranks form a total order), so cnt == k.
// ---------------------------------------------------------------------------
__global__ void k_select_pool(const float* __restrict__ x,
                              float* __restrict__ out) {
    __shared__ float sc[MAXSEG];
    __shared__ float sw[MAXSEG];
    __shared__ float psum[4][64];

    int g = blockIdx.x;
    int start = d_starts[g];
    int n = d_starts[g + 1] - start;
    int t = threadIdx.x;
    int k = (n + 1) >> 1;               // ceil(0.5 * n)

    if (n <= MAXSEG) {
        for (int i = t; i < n; i += 256) sc[i] = d_score[start + i];
        __syncthreads();
        for (int i = t; i < n; i += 256) {
            float si = sc[i];
            int cnt = 0;
            for (int j = 0; j < n; ++j) {
                float sj = sc[j];
                cnt += (sj > si) || (sj == si && j < i);
            }
            sw[i] = (cnt < k) ? si : 0.0f;
        }
        __syncthreads();

        int col = t & 63, rg = t >> 6;
        float acc = 0.0f;
        for (int row = rg; row < n; row += 4) {
            float w = sw[row];
            if (w != 0.0f) acc += w * x[(size_t)(start + row) * 64 + col];
        }
        psum[rg][col] = acc;
        __syncthreads();
        if (t < 64) {
            float num = psum[0][t] + psum[1][t] + psum[2][t] + psum[3][t];
            out[g * 64 + t] = num / fmaxf((float)k, 1.0f);
        }
    } else {
        // Fallback for improbably huge segments: rank via global memory,
        // stash weights in d_s (done with it by now).
        for (int i = t; i < n; i += 256) {
            float si = d_score[start + i];
            int cnt = 0;
            for (int j = 0; j < n; ++j) {
                float sj = d_score[start + j];
                cnt += (sj > si) || (sj == si && j < i);
            }
            d_s[start + i] = (cnt < k) ? si : 0.0f;
        }
        __syncthreads();
        int col = t & 63, rg = t >> 6;
        float acc = 0.0f;
        for (int row = rg; row < n; row += 4) {
            float w = d_s[start + row];
            if (w != 0.0f) acc += w * x[(size_t)(start + row) * 64 + col];
        }
        psum[rg][col] = acc;
        __syncthreads();
        if (t < 64) {
            float num = psum[0][t] + psum[1][t] + psum[2][t] + psum[3][t];
            out[g * 64 + t] = num / fmaxf((float)k, 1.0f);
        }
    }
}

// ---------------------------------------------------------------------------
extern "C" void kernel_launch(void* const* d_in, const int* in_sizes, int n_in,
                              void* d_out, int out_size) {
    const float* x      = (const float*)d_in[0];
    const int*   ei     = (const int*)d_in[1];
    const int*   batch  = (const int*)d_in[2];
    const float* w_rel  = (const float*)d_in[3];
    const float* b_rel  = (const float*)d_in[4];
    const float* w_root = (const float*)d_in[5];
    float*       out    = (float*)d_out;

    int N = in_sizes[2];
    int E = in_sizes[1] / 2;

    {
        long long threads = (long long)N * 32;
        int blocks = (int)((threads + 255) / 256);
        k_node_dots<<<blocks, 256>>>(x, w_rel, w_root, N);
    }
    if ((E & 3) == 0 && E > 0) {
        int E4 = E >> 2;
        k_edge_scatter4<<<(E4 + 255) / 256, 256>>>(ei, E);
    } else if (E > 0) {
        k_edge_scatter1<<<(E + 255) / 256, 256>>>(ei, E);
    }
    k_score_starts<<<(N + 255) / 256, 256>>>(batch, b_rel, N);
    k_select_pool<<<NGRAPH, 256>>>(x, out);
}